// round 2
// baseline (speedup 1.0000x reference)
#include <cuda_runtime.h>

#define NN      10000       // nodes
#define NBATCH  16          // batch
#define FDIM    128         // feature dim (64 input + 64 hidden)
#define ROWSZ   2048        // NBATCH * FDIM, floats per node-row
#define NE      160000      // edges
#define ODIM    128         // output dim
#define KDIM    384         // FDIM * 3 matrices
#define MROWS   160000      // NBATCH * NN
#define INSZ    640000      // NN * 64, per-batch stride of inputs/state

// ---- scratch (static device globals; no allocation) ----
__device__ float g_x0[NN * ROWSZ];
__device__ float g_x1[NN * ROWSZ];
__device__ float g_x2[NN * ROWSZ];
__device__ float g_wp[KDIM * ODIM];
__device__ int   g_rowptr[NN + 1];

// ============================================================
// Kernel 1: build x0[n][b][f] from inputs[b, n*64+f] / state
// ============================================================
__global__ void build_x0_kernel(const float* __restrict__ in,
                                const float* __restrict__ st) {
    int id = blockIdx.x * blockDim.x + threadIdx.x;   // float4 units
    if (id >= NN * ROWSZ / 4) return;
    int f4 = id & 31;            // 32 float4 per (n,b)
    int b  = (id >> 5) & 15;
    int n  = id >> 9;
    int f  = f4 << 2;
    const float* src = (f < 64) ? (in + b * INSZ + n * 64 + f)
                                : (st + b * INSZ + n * 64 + (f - 64));
    reinterpret_cast<float4*>(g_x0)[id] = *reinterpret_cast<const float4*>(src);
}

// ============================================================
// Kernel 2: CSR row pointers from sorted COO rows
// ============================================================
__global__ void build_rowptr_kernel(const int* __restrict__ rows) {
    int e = blockIdx.x * blockDim.x + threadIdx.x;
    if (e >= NE) return;
    int r = rows[e];
    int rprev = (e == 0) ? -1 : rows[e - 1];
    for (int rr = rprev + 1; rr <= r; ++rr) g_rowptr[rr] = e;
    if (e == NE - 1) {
        for (int rr = r + 1; rr <= NN; ++rr) g_rowptr[rr] = NE;
    }
}

// ============================================================
// Kernel 3: permute weight W[f*3+m][o] -> W'[m*128+f][o]
// ============================================================
__global__ void reorder_w_kernel(const float* __restrict__ w) {
    int id = blockIdx.x * blockDim.x + threadIdx.x;  // 384*128 = 49152
    if (id >= KDIM * ODIM) return;
    int o = id & 127;
    int k = id >> 7;         // 0..383
    int m = k >> 7;          // which diffusion matrix
    int f = k & 127;         // feature index
    g_wp[id] = w[(f * 3 + m) * ODIM + o];
}

// ============================================================
// Kernel 4: SpMM (CSR, 2 blocks per row, 256 thr x 4 floats)
//   mode 0:  g_x1[r] =      sum_e v * g_x0[c]
//   mode 1:  g_x2[r] = 2 *  sum_e v * g_x1[c]  - g_x0[r]
// ============================================================
__global__ __launch_bounds__(256) void spmm_kernel(const int* __restrict__ cols,
                                                   const float* __restrict__ vals,
                                                   int mode) {
    const float* __restrict__ z = mode ? g_x1 : g_x0;
    float* __restrict__ out     = mode ? g_x2 : g_x1;
    const float alpha           = mode ? 2.0f : 1.0f;

    int r    = blockIdx.x >> 1;          // node row
    int half = blockIdx.x & 1;           // which 1024-float half
    int t    = threadIdx.x + half * 256; // float4 index within row: 0..511
    int e0 = g_rowptr[r];
    int e1 = g_rowptr[r + 1];
    int base = r * ROWSZ;

    float4 acc = make_float4(0.f, 0.f, 0.f, 0.f);
    if (mode) {
        float4 s = reinterpret_cast<const float4*>(g_x0 + base)[t];
        acc.x = -s.x; acc.y = -s.y; acc.z = -s.z; acc.w = -s.w;
    }

    for (int e = e0; e < e1; ++e) {
        int   c = __ldg(&cols[e]);
        float v = alpha * __ldg(&vals[e]);
        float4 a = reinterpret_cast<const float4*>(z + c * ROWSZ)[t];
        acc.x += v * a.x; acc.y += v * a.y; acc.z += v * a.z; acc.w += v * a.w;
    }

    reinterpret_cast<float4*>(out + base)[t] = acc;
}

// ============================================================
// Kernel 5: GEMM  out[r, o] = bias[o] + sum_k A[r,k] * W'[k,o]
//   A[r, k] with k = m*128+f  ->  X_m[n*2048 + b*128 + f], r = b*NN + n
//   BM=128 BN=128 BK=16, 256 threads, 8x8 microtile, double-buffered
// ============================================================
__global__ __launch_bounds__(256, 2) void gemm_kernel(const float* __restrict__ bias,
                                                      float* __restrict__ out) {
    __shared__ float As[2][16][128];
    __shared__ float Bs[2][16][128];

    const int tid = threadIdx.x;
    const int r0  = blockIdx.x * 128;
    const int tx  = tid & 15;
    const int ty  = tid >> 4;

    // A staging: each thread loads 2 rows x 1 float4 (k-quad) per chunk
    const int rowA0 = tid >> 2;          // 0..63
    const int rowA1 = rowA0 + 64;
    const int kq    = (tid & 3) << 2;    // 0,4,8,12

    int rg0 = r0 + rowA0;
    int b0  = rg0 / NN;
    int base0 = (rg0 - b0 * NN) * ROWSZ + b0 * FDIM;
    int rg1 = r0 + rowA1;
    int b1  = rg1 / NN;
    int base1 = (rg1 - b1 * NN) * ROWSZ + b1 * FDIM;

    // B staging: each thread loads 2 k-rows x 1 float4 per chunk
    const int krow0 = tid >> 5;          // 0..7
    const int krow1 = krow0 + 8;
    const int c4    = (tid & 31) << 2;   // 0..124

    float acc[8][8];
    #pragma unroll
    for (int i = 0; i < 8; ++i)
        #pragma unroll
        for (int j = 0; j < 8; ++j)
            acc[i][j] = 0.f;

    // ---- prologue: chunk 0 (m=0, f0=0) ----
    {
        const float* X = g_x0;
        float4 a0 = *reinterpret_cast<const float4*>(X + base0 + kq);
        float4 a1 = *reinterpret_cast<const float4*>(X + base1 + kq);
        float4 w0 = *reinterpret_cast<const float4*>(g_wp + krow0 * ODIM + c4);
        float4 w1 = *reinterpret_cast<const float4*>(g_wp + krow1 * ODIM + c4);
        As[0][kq + 0][rowA0] = a0.x; As[0][kq + 1][rowA0] = a0.y;
        As[0][kq + 2][rowA0] = a0.z; As[0][kq + 3][rowA0] = a0.w;
        As[0][kq + 0][rowA1] = a1.x; As[0][kq + 1][rowA1] = a1.y;
        As[0][kq + 2][rowA1] = a1.z; As[0][kq + 3][rowA1] = a1.w;
        *reinterpret_cast<float4*>(&Bs[0][krow0][c4]) = w0;
        *reinterpret_cast<float4*>(&Bs[0][krow1][c4]) = w1;
    }
    __syncthreads();

    #pragma unroll 1
    for (int kc = 0; kc < 24; ++kc) {
        const int cur = kc & 1;
        float4 na0, na1, nw0, nw1;
        if (kc < 23) {
            int kn = kc + 1;
            int m  = kn >> 3;             // (kn*16)/128
            int f0 = (kn & 7) << 4;
            const float* Xn = (m == 0) ? g_x0 : (m == 1) ? g_x1 : g_x2;
            na0 = *reinterpret_cast<const float4*>(Xn + base0 + f0 + kq);
            na1 = *reinterpret_cast<const float4*>(Xn + base1 + f0 + kq);
            int k0n = kn << 4;
            nw0 = *reinterpret_cast<const float4*>(g_wp + (k0n + krow0) * ODIM + c4);
            nw1 = *reinterpret_cast<const float4*>(g_wp + (k0n + krow1) * ODIM + c4);
        }

        #pragma unroll
        for (int k = 0; k < 16; ++k) {
            float a[8], b[8];
            *reinterpret_cast<float4*>(&a[0]) = *reinterpret_cast<const float4*>(&As[cur][k][ty * 8]);
            *reinterpret_cast<float4*>(&a[4]) = *reinterpret_cast<const float4*>(&As[cur][k][ty * 8 + 4]);
            *reinterpret_cast<float4*>(&b[0]) = *reinterpret_cast<const float4*>(&Bs[cur][k][tx * 8]);
            *reinterpret_cast<float4*>(&b[4]) = *reinterpret_cast<const float4*>(&Bs[cur][k][tx * 8 + 4]);
            #pragma unroll
            for (int i = 0; i < 8; ++i)
                #pragma unroll
                for (int j = 0; j < 8; ++j)
                    acc[i][j] += a[i] * b[j];
        }

        if (kc < 23) {
            const int nxt = cur ^ 1;
            As[nxt][kq + 0][rowA0] = na0.x; As[nxt][kq + 1][rowA0] = na0.y;
            As[nxt][kq + 2][rowA0] = na0.z; As[nxt][kq + 3][rowA0] = na0.w;
            As[nxt][kq + 0][rowA1] = na1.x; As[nxt][kq + 1][rowA1] = na1.y;
            As[nxt][kq + 2][rowA1] = na1.z; As[nxt][kq + 3][rowA1] = na1.w;
            *reinterpret_cast<float4*>(&Bs[nxt][krow0][c4]) = nw0;
            *reinterpret_cast<float4*>(&Bs[nxt][krow1][c4]) = nw1;
            __syncthreads();
        }
    }

    // ---- epilogue: bias + store ----
    float bvals[8];
    *reinterpret_cast<float4*>(&bvals[0]) = *reinterpret_cast<const float4*>(bias + tx * 8);
    *reinterpret_cast<float4*>(&bvals[4]) = *reinterpret_cast<const float4*>(bias + tx * 8 + 4);

    #pragma unroll
    for (int i = 0; i < 8; ++i) {
        int rr = r0 + ty * 8 + i;
        float4 o0, o1;
        o0.x = acc[i][0] + bvals[0]; o0.y = acc[i][1] + bvals[1];
        o0.z = acc[i][2] + bvals[2]; o0.w = acc[i][3] + bvals[3];
        o1.x = acc[i][4] + bvals[4]; o1.y = acc[i][5] + bvals[5];
        o1.z = acc[i][6] + bvals[6]; o1.w = acc[i][7] + bvals[7];
        *reinterpret_cast<float4*>(out + rr * ODIM + tx * 8)     = o0;
        *reinterpret_cast<float4*>(out + rr * ODIM + tx * 8 + 4) = o1;
    }
}

// ============================================================
// Launch
// ============================================================
extern "C" void kernel_launch(void* const* d_in, const int* in_sizes, int n_in,
                              void* d_out, int out_size) {
    const float* inputs = (const float*)d_in[0];
    const float* state  = (const float*)d_in[1];
    const int*   rows   = (const int*)  d_in[2];
    const int*   cols   = (const int*)  d_in[3];
    const float* vals   = (const float*)d_in[4];
    const float* weight = (const float*)d_in[5];
    const float* biases = (const float*)d_in[6];
    float* out = (float*)d_out;

    build_x0_kernel<<<(NN * ROWSZ / 4 + 255) / 256, 256>>>(inputs, state);
    build_rowptr_kernel<<<(NE + 255) / 256, 256>>>(rows);
    reorder_w_kernel<<<(KDIM * ODIM + 255) / 256, 256>>>(weight);
    spmm_kernel<<<NN * 2, 256>>>(cols, vals, 0);
    spmm_kernel<<<NN * 2, 256>>>(cols, vals, 1);
    gemm_kernel<<<MROWS / 128, 256>>>(biases, out);
}

// round 3
// speedup vs baseline: 1.6068x; 1.6068x over previous
#include <cuda_runtime.h>
#include <cstdint>

#define NN      10000       // nodes
#define NBATCH  16          // batch
#define FDIM    128         // feature dim (64 input + 64 hidden)
#define ROWSZ   2048        // NBATCH * FDIM, floats per node-row
#define NE      160000      // edges
#define ODIM    128         // output dim
#define KDIM    384         // FDIM * 3 matrices
#define MROWS   160000      // NBATCH * NN
#define INSZ    640000      // NN * 64, per-batch stride of inputs/state

// ---- scratch (static device globals; no allocation) ----
__device__ float g_x0[NN * ROWSZ];
__device__ float g_x1[NN * ROWSZ];
__device__ float g_x2[NN * ROWSZ];
__device__ float g_wp[KDIM * ODIM];
__device__ int   g_rowptr[NN + 1];

// ============================================================
// Kernel 1: build x0[n][b][f] from inputs[b, n*64+f] / state
// ============================================================
__global__ void build_x0_kernel(const float* __restrict__ in,
                                const float* __restrict__ st) {
    int id = blockIdx.x * blockDim.x + threadIdx.x;   // float4 units
    if (id >= NN * ROWSZ / 4) return;
    int f4 = id & 31;            // 32 float4 per (n,b)
    int b  = (id >> 5) & 15;
    int n  = id >> 9;
    int f  = f4 << 2;
    const float* src = (f < 64) ? (in + b * INSZ + n * 64 + f)
                                : (st + b * INSZ + n * 64 + (f - 64));
    reinterpret_cast<float4*>(g_x0)[id] = *reinterpret_cast<const float4*>(src);
}

// ============================================================
// Kernel 2: CSR row pointers from sorted COO rows
// ============================================================
__global__ void build_rowptr_kernel(const int* __restrict__ rows) {
    int e = blockIdx.x * blockDim.x + threadIdx.x;
    if (e >= NE) return;
    int r = rows[e];
    int rprev = (e == 0) ? -1 : rows[e - 1];
    for (int rr = rprev + 1; rr <= r; ++rr) g_rowptr[rr] = e;
    if (e == NE - 1) {
        for (int rr = r + 1; rr <= NN; ++rr) g_rowptr[rr] = NE;
    }
}

// ============================================================
// Kernel 3: permute weight W[f*3+m][o] -> W'[m*128+f][o]
// ============================================================
__global__ void reorder_w_kernel(const float* __restrict__ w) {
    int id = blockIdx.x * blockDim.x + threadIdx.x;  // 384*128 = 49152
    if (id >= KDIM * ODIM) return;
    int o = id & 127;
    int k = id >> 7;         // 0..383
    int m = k >> 7;          // which diffusion matrix
    int f = k & 127;         // feature index
    g_wp[id] = w[(f * 3 + m) * ODIM + o];
}

// ============================================================
// Kernel 4: SpMM (CSR, 2 blocks per row, 256 thr x 4 floats)
//   unrolled x2 with dual accumulators for MLP
// ============================================================
__global__ __launch_bounds__(256) void spmm_kernel(const int* __restrict__ cols,
                                                   const float* __restrict__ vals,
                                                   int mode) {
    const float* __restrict__ z = mode ? g_x1 : g_x0;
    float* __restrict__ out     = mode ? g_x2 : g_x1;
    const float alpha           = mode ? 2.0f : 1.0f;

    int r    = blockIdx.x >> 1;          // node row
    int half = blockIdx.x & 1;           // which 1024-float half
    int t    = threadIdx.x + half * 256; // float4 index within row: 0..511
    int e0 = g_rowptr[r];
    int e1 = g_rowptr[r + 1];
    int base = r * ROWSZ;

    float4 acc0 = make_float4(0.f, 0.f, 0.f, 0.f);
    float4 acc1 = make_float4(0.f, 0.f, 0.f, 0.f);
    if (mode) {
        float4 s = reinterpret_cast<const float4*>(g_x0 + base)[t];
        acc0.x = -s.x; acc0.y = -s.y; acc0.z = -s.z; acc0.w = -s.w;
    }

    const float4* z4 = reinterpret_cast<const float4*>(z);
    int e = e0;
    for (; e + 1 < e1; e += 2) {
        int   c0 = __ldg(&cols[e]);
        int   c1 = __ldg(&cols[e + 1]);
        float v0 = alpha * __ldg(&vals[e]);
        float v1 = alpha * __ldg(&vals[e + 1]);
        float4 a = z4[c0 * 512 + t];
        float4 b = z4[c1 * 512 + t];
        acc0.x += v0 * a.x; acc0.y += v0 * a.y; acc0.z += v0 * a.z; acc0.w += v0 * a.w;
        acc1.x += v1 * b.x; acc1.y += v1 * b.y; acc1.z += v1 * b.z; acc1.w += v1 * b.w;
    }
    if (e < e1) {
        int   c0 = __ldg(&cols[e]);
        float v0 = alpha * __ldg(&vals[e]);
        float4 a = z4[c0 * 512 + t];
        acc0.x += v0 * a.x; acc0.y += v0 * a.y; acc0.z += v0 * a.z; acc0.w += v0 * a.w;
    }
    acc0.x += acc1.x; acc0.y += acc1.y; acc0.z += acc1.z; acc0.w += acc1.w;

    reinterpret_cast<float4*>(out + base)[t] = acc0;
}

// ============================================================
// bf16-split helpers for 3xMMA fp32 emulation
// ============================================================
__device__ __forceinline__ void split2(float e /*k even*/, float o /*k odd*/,
                                       uint32_t& h, uint32_t& l) {
    uint32_t hh;
    asm("cvt.rn.bf16x2.f32 %0, %1, %2;" : "=r"(hh) : "f"(o), "f"(e));
    float he = __uint_as_float(hh << 16);
    float ho = __uint_as_float(hh & 0xffff0000u);
    uint32_t ll;
    asm("cvt.rn.bf16x2.f32 %0, %1, %2;" : "=r"(ll) : "f"(o - ho), "f"(e - he));
    h = hh; l = ll;
}

__device__ __forceinline__ void mma16816(float c[4], const uint32_t a[4], const uint32_t b[2]) {
    asm("mma.sync.aligned.m16n8k16.row.col.f32.bf16.bf16.f32 "
        "{%0,%1,%2,%3},{%4,%5,%6,%7},{%8,%9},{%0,%1,%2,%3};"
        : "+f"(c[0]), "+f"(c[1]), "+f"(c[2]), "+f"(c[3])
        : "r"(a[0]), "r"(a[1]), "r"(a[2]), "r"(a[3]), "r"(b[0]), "r"(b[1]));
}

// ============================================================
// Kernel 5: GEMM  out[r, o] = bias[o] + sum_k A[r,k] * W'[k,o]
//   BM=128 BN=128 BK=16, 256 threads (8 warps 2x4), tensor cores
//   bf16-split 3xMMA (hi*hi + lo*hi + hi*lo) ~ fp32 accuracy
// ============================================================
__global__ __launch_bounds__(256) void gemm_kernel(const float* __restrict__ bias,
                                                   float* __restrict__ out) {
    __shared__ float As[2][16][132];   // [k][m], pad->132 (conflict-free frag LDS)
    __shared__ float Bs[2][16][132];   // [k][n]

    const int tid  = threadIdx.x;
    const int r0   = blockIdx.x * 128;
    const int lane = tid & 31;
    const int wid  = tid >> 5;
    const int wm   = wid & 1;          // warp row  (64 rows each)
    const int wn   = wid >> 1;         // warp col  (32 cols each)
    const int rp   = lane >> 2;        // 0..7
    const int c2   = (lane & 3) << 1;  // 0,2,4,6

    // ---- staging indices (A: 2 rows x float4-k per thread; B: 2 k-rows x float4-n) ----
    const int rowA0 = tid >> 2;          // 0..63
    const int rowA1 = rowA0 + 64;
    const int kq    = (tid & 3) << 2;    // 0,4,8,12

    int rg0 = r0 + rowA0;
    int b0  = rg0 / NN;
    int base0 = (rg0 - b0 * NN) * ROWSZ + b0 * FDIM;
    int rg1 = r0 + rowA1;
    int b1  = rg1 / NN;
    int base1 = (rg1 - b1 * NN) * ROWSZ + b1 * FDIM;

    const int krow0 = tid >> 5;          // 0..7
    const int krow1 = krow0 + 8;
    const int c4    = (tid & 31) << 2;   // 0..124

    float C[4][4][4];
    #pragma unroll
    for (int i = 0; i < 4; ++i)
        #pragma unroll
        for (int j = 0; j < 4; ++j)
            #pragma unroll
            for (int q = 0; q < 4; ++q)
                C[i][j][q] = 0.f;

    // ---- prologue: chunk 0 (m=0, f0=0) ----
    {
        float4 a0 = *reinterpret_cast<const float4*>(g_x0 + base0 + kq);
        float4 a1 = *reinterpret_cast<const float4*>(g_x0 + base1 + kq);
        float4 w0 = *reinterpret_cast<const float4*>(g_wp + krow0 * ODIM + c4);
        float4 w1 = *reinterpret_cast<const float4*>(g_wp + krow1 * ODIM + c4);
        As[0][kq + 0][rowA0] = a0.x; As[0][kq + 1][rowA0] = a0.y;
        As[0][kq + 2][rowA0] = a0.z; As[0][kq + 3][rowA0] = a0.w;
        As[0][kq + 0][rowA1] = a1.x; As[0][kq + 1][rowA1] = a1.y;
        As[0][kq + 2][rowA1] = a1.z; As[0][kq + 3][rowA1] = a1.w;
        *reinterpret_cast<float4*>(&Bs[0][krow0][c4]) = w0;
        *reinterpret_cast<float4*>(&Bs[0][krow1][c4]) = w1;
    }
    __syncthreads();

    #pragma unroll 1
    for (int kc = 0; kc < 24; ++kc) {
        const int cur = kc & 1;
        float4 na0, na1, nw0, nw1;
        if (kc < 23) {
            int kn = kc + 1;
            int m  = kn >> 3;
            int f0 = (kn & 7) << 4;
            const float* Xn = (m == 0) ? g_x0 : (m == 1) ? g_x1 : g_x2;
            na0 = *reinterpret_cast<const float4*>(Xn + base0 + f0 + kq);
            na1 = *reinterpret_cast<const float4*>(Xn + base1 + f0 + kq);
            int k0n = kn << 4;
            nw0 = *reinterpret_cast<const float4*>(g_wp + (k0n + krow0) * ODIM + c4);
            nw1 = *reinterpret_cast<const float4*>(g_wp + (k0n + krow1) * ODIM + c4);
        }

        // ---- load + split fragments (one k16 step per chunk) ----
        uint32_t Ahi[4][4], Alo[4][4], Bhi[4][2], Blo[4][2];
        #pragma unroll
        for (int i = 0; i < 4; ++i) {
            int r = wm * 64 + i * 16 + rp;
            float xa0 = As[cur][c2    ][r],     xa1 = As[cur][c2 + 1][r];
            float xb0 = As[cur][c2    ][r + 8], xb1 = As[cur][c2 + 1][r + 8];
            float xc0 = As[cur][c2 + 8][r],     xc1 = As[cur][c2 + 9][r];
            float xd0 = As[cur][c2 + 8][r + 8], xd1 = As[cur][c2 + 9][r + 8];
            split2(xa0, xa1, Ahi[i][0], Alo[i][0]);
            split2(xb0, xb1, Ahi[i][1], Alo[i][1]);
            split2(xc0, xc1, Ahi[i][2], Alo[i][2]);
            split2(xd0, xd1, Ahi[i][3], Alo[i][3]);
        }
        #pragma unroll
        for (int j = 0; j < 4; ++j) {
            int n = wn * 32 + j * 8 + rp;
            float y0 = Bs[cur][c2    ][n], y1 = Bs[cur][c2 + 1][n];
            float y2 = Bs[cur][c2 + 8][n], y3 = Bs[cur][c2 + 9][n];
            split2(y0, y1, Bhi[j][0], Blo[j][0]);
            split2(y2, y3, Bhi[j][1], Blo[j][1]);
        }

        // ---- 3xMMA per tile ----
        #pragma unroll
        for (int i = 0; i < 4; ++i)
            #pragma unroll
            for (int j = 0; j < 4; ++j) {
                mma16816(C[i][j], Alo[i], Bhi[j]);
                mma16816(C[i][j], Ahi[i], Blo[j]);
                mma16816(C[i][j], Ahi[i], Bhi[j]);
            }

        if (kc < 23) {
            const int nxt = cur ^ 1;
            As[nxt][kq + 0][rowA0] = na0.x; As[nxt][kq + 1][rowA0] = na0.y;
            As[nxt][kq + 2][rowA0] = na0.z; As[nxt][kq + 3][rowA0] = na0.w;
            As[nxt][kq + 0][rowA1] = na1.x; As[nxt][kq + 1][rowA1] = na1.y;
            As[nxt][kq + 2][rowA1] = na1.z; As[nxt][kq + 3][rowA1] = na1.w;
            *reinterpret_cast<float4*>(&Bs[nxt][krow0][c4]) = nw0;
            *reinterpret_cast<float4*>(&Bs[nxt][krow1][c4]) = nw1;
            __syncthreads();
        }
    }

    // ---- epilogue: bias + store (fragment layout) ----
    #pragma unroll
    for (int j = 0; j < 4; ++j) {
        int col = wn * 32 + j * 8 + c2;
        float2 bv = *reinterpret_cast<const float2*>(bias + col);
        #pragma unroll
        for (int i = 0; i < 4; ++i) {
            int r = r0 + wm * 64 + i * 16 + rp;
            float2 o0, o1;
            o0.x = C[i][j][0] + bv.x; o0.y = C[i][j][1] + bv.y;
            o1.x = C[i][j][2] + bv.x; o1.y = C[i][j][3] + bv.y;
            *reinterpret_cast<float2*>(out + r * ODIM + col)       = o0;
            *reinterpret_cast<float2*>(out + (r + 8) * ODIM + col) = o1;
        }
    }
}

// ============================================================
// Launch
// ============================================================
extern "C" void kernel_launch(void* const* d_in, const int* in_sizes, int n_in,
                              void* d_out, int out_size) {
    const float* inputs = (const float*)d_in[0];
    const float* state  = (const float*)d_in[1];
    const int*   rows   = (const int*)  d_in[2];
    const int*   cols   = (const int*)  d_in[3];
    const float* vals   = (const float*)d_in[4];
    const float* weight = (const float*)d_in[5];
    const float* biases = (const float*)d_in[6];
    float* out = (float*)d_out;

    build_x0_kernel<<<(NN * ROWSZ / 4 + 255) / 256, 256>>>(inputs, state);
    build_rowptr_kernel<<<(NE + 255) / 256, 256>>>(rows);
    reorder_w_kernel<<<(KDIM * ODIM + 255) / 256, 256>>>(weight);
    spmm_kernel<<<NN * 2, 256>>>(cols, vals, 0);
    spmm_kernel<<<NN * 2, 256>>>(cols, vals, 1);
    gemm_kernel<<<MROWS / 128, 256>>>(biases, out);
}